// round 7
// baseline (speedup 1.0000x reference)
#include <cuda_runtime.h>
#include <cuda_bf16.h>
#include <cstdint>

#define BB 16
#define NN 576
#define DD 1024
#define HH 16
#define HD 64

// ---------------- scratch (static device globals; no allocation) ----------------
__device__ float g_qk[(long)BB * NN * 2 * DD];        // [B,N,2D]
__device__ float g_v[(long)BB * NN * DD];             // [B,N,D]
__device__ float g_pos[(long)HH * NN * NN];           // [H,N,N]
__device__ float g_o[(long)BB * NN * DD];             // [B,N,D]

// ---------------- helpers ------------------------------------------------------
__device__ __forceinline__ float to_tf32(float x) {
    unsigned r;
    asm("cvt.rna.tf32.f32 %0, %1;" : "=r"(r) : "f"(x));
    return __uint_as_float(r);
}

__device__ __forceinline__ void mma_tf32(float& d0, float& d1, float& d2, float& d3,
                                         float a0, float a1, float a2, float a3,
                                         float b0, float b1) {
    asm volatile(
        "mma.sync.aligned.m16n8k8.row.col.f32.tf32.tf32.f32 "
        "{%0,%1,%2,%3}, {%4,%5,%6,%7}, {%8,%9}, {%0,%1,%2,%3};\n"
        : "+f"(d0), "+f"(d1), "+f"(d2), "+f"(d3)
        : "r"(__float_as_uint(a0)), "r"(__float_as_uint(a1)),
          "r"(__float_as_uint(a2)), "r"(__float_as_uint(a3)),
          "r"(__float_as_uint(b0)), "r"(__float_as_uint(b1)));
}

__device__ __forceinline__ void mma_bf16(float& d0, float& d1, float& d2, float& d3,
                                         unsigned a0, unsigned a1, unsigned a2, unsigned a3,
                                         unsigned b0, unsigned b1) {
    asm volatile(
        "mma.sync.aligned.m16n8k16.row.col.f32.bf16.bf16.f32 "
        "{%0,%1,%2,%3}, {%4,%5,%6,%7}, {%8,%9}, {%0,%1,%2,%3};\n"
        : "+f"(d0), "+f"(d1), "+f"(d2), "+f"(d3)
        : "r"(a0), "r"(a1), "r"(a2), "r"(a3), "r"(b0), "r"(b1));
}

__device__ __forceinline__ unsigned packbf2(__nv_bfloat16 x, __nv_bfloat16 y) {
    __nv_bfloat162 t;
    t.x = x; t.y = y;
    return *reinterpret_cast<unsigned*>(&t);
}

// ---------------- tf32 GEMM, double-buffered, A in fragment-permuted layout ----
// A stage: float4[2 wmIdx][4 ma][4 kk][8 gp][4 tg'] where tg' = tg ^ kk (bank skew)
// and the float4 = {A[mr][kb+tg], A[mr+8][kb+tg], A[mr][kb+tg+4], A[mr+8][kb+tg+4]}.
// One LDS.128 per fragment instead of 4 scalar LDS. B stays [32][136] scalar.
#define GBM 128
#define GBN 128
#define GBK 32
#define BS_STRIDE 136
#define AS_STAGE 4096                         // floats (1024 float4)
#define BS_STAGE (GBK * BS_STRIDE)            // 4352 floats
#define GS_SMEM ((2 * AS_STAGE + 2 * BS_STAGE) * 4)   // 67584 B

template <bool BIAS>
__global__ __launch_bounds__(256, 2) void gemm_tf32(const float* __restrict__ A,
                                                    const float* __restrict__ W,
                                                    const float* __restrict__ bias,
                                                    float* __restrict__ C,
                                                    int M, int K, int Ncols) {
    extern __shared__ float gsm[];
    float* As0 = gsm;                        // 2 stages, 4096 floats each
    float* Bs0 = gsm + 2 * AS_STAGE;         // 2 stages, [32][136]

    const int tid = threadIdx.x;
    const int warp = tid >> 5, lane = tid & 31;
    const int wmIdx = warp & 1;              // A m-half
    const int wn = (warp >> 1) * 32;
    const int gp = lane >> 2, tg = lane & 3;

    const int bm = blockIdx.y * GBM, bn = blockIdx.x * GBN;

    float acc[4][4][4];
#pragma unroll
    for (int i = 0; i < 4; i++)
#pragma unroll
        for (int j = 0; j < 4; j++)
#pragma unroll
            for (int r = 0; r < 4; r++) acc[i][j][r] = 0.0f;

    float4 aStage[4], bStage[4];
    const float* Abase = A + (long)bm * K;
    const float* Wbase = W + bn;

#define LOAD_STAGE(k0)                                                          \
    {                                                                           \
        _Pragma("unroll") for (int i = 0; i < 4; i++) {                         \
            int idx = tid + 256 * i;                                            \
            aStage[i] = *(const float4*)(Abase + (long)(idx >> 3) * K + (k0) +  \
                                         (idx & 7) * 4);                        \
            bStage[i] = *(const float4*)(Wbase + (long)((k0) + (idx >> 5)) *    \
                                         Ncols + (idx & 31) * 4);               \
        }                                                                       \
    }

    // A write: element (ar, c) -> fbase + ((tg^kk)<<2) + comp
    //   fbase = ((((ar>>6)*4 + ((ar>>4)&3))*4 + kk)*8 + (ar&7))*16 + sub + 2*half
#define STORE_STAGE(s)                                                          \
    {                                                                           \
        float* Ad = As0 + (s) * AS_STAGE;                                       \
        float* Bd = Bs0 + (s) * BS_STAGE;                                       \
        _Pragma("unroll") for (int i = 0; i < 4; i++) {                         \
            int idx = tid + 256 * i;                                            \
            int ar = idx >> 3, ac = (idx & 7) * 4;                              \
            int kk = ac >> 3, half = (ac >> 2) & 1;                             \
            int fbase = ((((ar >> 6) * 4 + ((ar >> 4) & 3)) * 4 + kk) * 8 +     \
                         (ar & 7)) * 16 + ((ar >> 3) & 1) + 2 * half;           \
            Ad[fbase + ((0 ^ kk) << 2)] = to_tf32(aStage[i].x);                 \
            Ad[fbase + ((1 ^ kk) << 2)] = to_tf32(aStage[i].y);                 \
            Ad[fbase + ((2 ^ kk) << 2)] = to_tf32(aStage[i].z);                 \
            Ad[fbase + ((3 ^ kk) << 2)] = to_tf32(aStage[i].w);                 \
            int br = idx >> 5, bc = (idx & 31) * 4;                             \
            Bd[br * BS_STRIDE + bc + 0] = to_tf32(bStage[i].x);                 \
            Bd[br * BS_STRIDE + bc + 1] = to_tf32(bStage[i].y);                 \
            Bd[br * BS_STRIDE + bc + 2] = to_tf32(bStage[i].z);                 \
            Bd[br * BS_STRIDE + bc + 3] = to_tf32(bStage[i].w);                 \
        }                                                                       \
    }

#define COMPUTE_CHUNK(s)                                                        \
    {                                                                           \
        const float4* Ar4 = (const float4*)(As0 + (s) * AS_STAGE);              \
        const float* Br = Bs0 + (s) * BS_STAGE;                                 \
        _Pragma("unroll") for (int kk = 0; kk < 4; kk++) {                      \
            const int kb = kk * 8;                                              \
            float4 af[4];                                                       \
            _Pragma("unroll") for (int ma = 0; ma < 4; ma++)                    \
                af[ma] = Ar4[(((wmIdx * 4 + ma) * 4 + kk) * 8 + gp) * 4 +       \
                             (tg ^ kk)];                                        \
            float bf[4][2];                                                     \
            _Pragma("unroll") for (int nb = 0; nb < 4; nb++) {                  \
                const int nc = wn + nb * 8 + gp;                                \
                bf[nb][0] = Br[(kb + tg) * BS_STRIDE + nc];                     \
                bf[nb][1] = Br[(kb + tg + 4) * BS_STRIDE + nc];                 \
            }                                                                   \
            _Pragma("unroll") for (int ma = 0; ma < 4; ma++)                    \
                _Pragma("unroll") for (int nb = 0; nb < 4; nb++)                \
                    mma_tf32(acc[ma][nb][0], acc[ma][nb][1], acc[ma][nb][2],    \
                             acc[ma][nb][3], af[ma].x, af[ma].y, af[ma].z,      \
                             af[ma].w, bf[nb][0], bf[nb][1]);                   \
        }                                                                       \
    }

    int s = 0;
    LOAD_STAGE(0);
    STORE_STAGE(0);
    __syncthreads();

    for (int k0 = GBK; k0 < K; k0 += GBK) {
        LOAD_STAGE(k0);
        COMPUTE_CHUNK(s);
        STORE_STAGE(s ^ 1);
        s ^= 1;
        __syncthreads();
    }
    COMPUTE_CHUNK(s);

#pragma unroll
    for (int ma = 0; ma < 4; ma++) {
        const long r0 = bm + wmIdx * 64 + ma * 16 + gp;
        const long r1 = r0 + 8;
#pragma unroll
        for (int nb = 0; nb < 4; nb++) {
            const int col = bn + wn + nb * 8 + tg * 2;
            float2 v0 = make_float2(acc[ma][nb][0], acc[ma][nb][1]);
            float2 v1 = make_float2(acc[ma][nb][2], acc[ma][nb][3]);
            if (BIAS) {
                const float bb0 = __ldg(bias + col), bb1 = __ldg(bias + col + 1);
                v0.x += bb0; v0.y += bb1;
                v1.x += bb0; v1.y += bb1;
            }
            *(float2*)(C + r0 * Ncols + col) = v0;
            *(float2*)(C + r1 * Ncols + col) = v1;
        }
    }
#undef LOAD_STAGE
#undef STORE_STAGE
#undef COMPUTE_CHUNK
}

// ---------------- positional softmax: pos[h,n,:] = softmax(rel@W_pos+b) --------
__global__ __launch_bounds__(256) void pos_kernel(const float* __restrict__ rel,
                                                  const float* __restrict__ Wp,
                                                  const float* __restrict__ bp,
                                                  float* __restrict__ pos) {
    const int n = blockIdx.x, h = blockIdx.y, tid = threadIdx.x;
    __shared__ float red[8];
    __shared__ float bcv;
    const float w0 = Wp[h], w1 = Wp[HH + h], w2 = Wp[2 * HH + h], bb = bp[h];
    const float* r = rel + (long)n * NN * 3;

    float s0, s1, s2 = -1e30f;
    {
        const float* p = r + tid * 3;
        s0 = p[0] * w0 + p[1] * w1 + p[2] * w2 + bb;
        p = r + (tid + 256) * 3;
        s1 = p[0] * w0 + p[1] * w1 + p[2] * w2 + bb;
        if (tid < 64) {
            p = r + (tid + 512) * 3;
            s2 = p[0] * w0 + p[1] * w1 + p[2] * w2 + bb;
        }
    }
    float mx = fmaxf(fmaxf(s0, s1), s2);
#pragma unroll
    for (int o = 16; o; o >>= 1) mx = fmaxf(mx, __shfl_xor_sync(~0u, mx, o));
    if ((tid & 31) == 0) red[tid >> 5] = mx;
    __syncthreads();
    if (tid == 0) {
        float m = red[0];
        for (int i = 1; i < 8; i++) m = fmaxf(m, red[i]);
        bcv = m;
    }
    __syncthreads();
    mx = bcv;
    float e0 = expf(s0 - mx), e1 = expf(s1 - mx);
    float e2 = (tid < 64) ? expf(s2 - mx) : 0.0f;
    float sum = e0 + e1 + e2;
#pragma unroll
    for (int o = 16; o; o >>= 1) sum += __shfl_xor_sync(~0u, sum, o);
    __syncthreads();
    if ((tid & 31) == 0) red[tid >> 5] = sum;
    __syncthreads();
    if (tid == 0) {
        float s = 0.f;
        for (int i = 0; i < 8; i++) s += red[i];
        bcv = 1.0f / s;
    }
    __syncthreads();
    const float inv = bcv;
    float* out = pos + ((long)h * NN + n) * NN;
    out[tid] = e0 * inv;
    out[tid + 256] = e1 * inv;
    if (tid < 64) out[tid + 512] = e2 * inv;
}

// ---------------- fused one-pass attention -------------------------------------
// Block = (b, h, 64 q-rows). S-phase: split-bf16 m16n8k16 (qh*kh + qh*kl + ql*kh).
// exp (no max-sub; logits bounded), O_c += e@v (tf32), O_p += pos@v (tf32),
// l += rowsum(e). Final: out = (1-g)*O_c/l + g*O_p.
#define QB 36
#define KS 72
#define QS 68
#define FA_SMEM ((4 * 64 * QB + 64 * KS + 64 * QS) * 4)   // 72704 B

__global__ __launch_bounds__(256, 2) void fused_attn(
    const float* __restrict__ qk, const float* __restrict__ v,
    const float* __restrict__ pos, const float* __restrict__ gating,
    float* __restrict__ o) {
    extern __shared__ float smem[];
    unsigned* qsb_h = (unsigned*)smem;          // [64][36] bf16x2 (d-pairs)
    unsigned* qsb_l = qsb_h + 64 * QB;
    unsigned* ksb_h = qsb_l + 64 * QB;          // [64][36] rows = seq
    unsigned* ksb_l = ksb_h + 64 * QB;
    float* vs = (float*)(ksb_l + 64 * QB);      // [64][72]
    float* ps = vs + 64 * KS;                   // [64][68]

    const int tid = threadIdx.x, warp = tid >> 5, lane = tid & 31;
    const int gp = lane >> 2, tg = lane & 3;
    const int wm = (warp & 3) * 16;             // warp's 16 q-rows
    const int wh = warp >> 2;                   // k-half (S cols wh*32..+32)
    const int n0 = blockIdx.x * 64;
    const int b = blockIdx.y >> 4, h = blockIdx.y & 15;

    const float* qbase = qk + (long)b * NN * 2048 + h * 64;
    const float* kbase = qbase + 1024;
    const float* vbase = v + (long)b * NN * DD + h * 64;
    const float* pbase = pos + ((long)h * NN + n0) * NN;

    // ---- load q tile (bf16 hi/lo split, packed pairs) ----
    {
        int idx = tid;
#pragma unroll
        for (int i = 0; i < 4; i++, idx += 256) {
            int r = idx >> 4, c4 = (idx & 15) * 4;
            float4 a = *(const float4*)(qbase + (long)(n0 + r) * 2048 + c4);
            __nv_bfloat16 h0 = __float2bfloat16_rn(a.x);
            __nv_bfloat16 h1 = __float2bfloat16_rn(a.y);
            __nv_bfloat16 h2 = __float2bfloat16_rn(a.z);
            __nv_bfloat16 h3 = __float2bfloat16_rn(a.w);
            qsb_h[r * QB + (c4 >> 1)]     = packbf2(h0, h1);
            qsb_h[r * QB + (c4 >> 1) + 1] = packbf2(h2, h3);
            qsb_l[r * QB + (c4 >> 1)]     = packbf2(
                __float2bfloat16_rn(a.x - __bfloat162float(h0)),
                __float2bfloat16_rn(a.y - __bfloat162float(h1)));
            qsb_l[r * QB + (c4 >> 1) + 1] = packbf2(
                __float2bfloat16_rn(a.z - __bfloat162float(h2)),
                __float2bfloat16_rn(a.w - __bfloat162float(h3)));
        }
    }

    float Oc[8][4], Op[8][4];
#pragma unroll
    for (int i = 0; i < 8; i++)
#pragma unroll
        for (int j = 0; j < 4; j++) { Oc[i][j] = 0.0f; Op[i][j] = 0.0f; }
    float l0 = 0.0f, l1 = 0.0f;
    const float scale = 0.125f;

    for (int m0 = 0; m0 < NN; m0 += 64) {
        __syncthreads();
        // ---- load k (bf16 hi/lo), v (tf32), pos (tf32) tiles ----
        {
            int idx = tid;
#pragma unroll
            for (int i = 0; i < 4; i++, idx += 256) {
                int r = idx >> 4, c4 = (idx & 15) * 4;
                float4 a = *(const float4*)(kbase + (long)(m0 + r) * 2048 + c4);
                __nv_bfloat16 h0 = __float2bfloat16_rn(a.x);
                __nv_bfloat16 h1 = __float2bfloat16_rn(a.y);
                __nv_bfloat16 h2 = __float2bfloat16_rn(a.z);
                __nv_bfloat16 h3 = __float2bfloat16_rn(a.w);
                ksb_h[r * QB + (c4 >> 1)]     = packbf2(h0, h1);
                ksb_h[r * QB + (c4 >> 1) + 1] = packbf2(h2, h3);
                ksb_l[r * QB + (c4 >> 1)]     = packbf2(
                    __float2bfloat16_rn(a.x - __bfloat162float(h0)),
                    __float2bfloat16_rn(a.y - __bfloat162float(h1)));
                ksb_l[r * QB + (c4 >> 1) + 1] = packbf2(
                    __float2bfloat16_rn(a.z - __bfloat162float(h2)),
                    __float2bfloat16_rn(a.w - __bfloat162float(h3)));
                float4 vv = *(const float4*)(vbase + (long)(m0 + r) * DD + c4);
                vs[r * KS + c4 + 0] = to_tf32(vv.x);
                vs[r * KS + c4 + 1] = to_tf32(vv.y);
                vs[r * KS + c4 + 2] = to_tf32(vv.z);
                vs[r * KS + c4 + 3] = to_tf32(vv.w);
                float4 pp = *(const float4*)(pbase + (long)r * NN + m0 + c4);
                ps[r * QS + c4 + 0] = to_tf32(pp.x);
                ps[r * QS + c4 + 1] = to_tf32(pp.y);
                ps[r * QS + c4 + 2] = to_tf32(pp.z);
                ps[r * QS + c4 + 3] = to_tf32(pp.w);
            }
        }
        __syncthreads();

        // ---- S = q @ k^T over warp's 16x32 slice (split-bf16, m16n8k16) ----
        float s[4][4];
#pragma unroll
        for (int i = 0; i < 4; i++)
#pragma unroll
            for (int j = 0; j < 4; j++) s[i][j] = 0.0f;

        const int rowA = (wm + gp) * QB;
#pragma unroll
        for (int kc = 0; kc < 4; kc++) {
            const int d2 = kc * 8 + tg;
            unsigned ah0 = qsb_h[rowA + d2];
            unsigned ah1 = qsb_h[rowA + 8 * QB + d2];
            unsigned ah2 = qsb_h[rowA + d2 + 4];
            unsigned ah3 = qsb_h[rowA + 8 * QB + d2 + 4];
            unsigned al0 = qsb_l[rowA + d2];
            unsigned al1 = qsb_l[rowA + 8 * QB + d2];
            unsigned al2 = qsb_l[rowA + d2 + 4];
            unsigned al3 = qsb_l[rowA + 8 * QB + d2 + 4];
#pragma unroll
            for (int na = 0; na < 4; na++) {
                const int rowB = (wh * 32 + na * 8 + gp) * QB;
                unsigned bh0 = ksb_h[rowB + d2];
                unsigned bh1 = ksb_h[rowB + d2 + 4];
                unsigned bl0 = ksb_l[rowB + d2];
                unsigned bl1 = ksb_l[rowB + d2 + 4];
                mma_bf16(s[na][0], s[na][1], s[na][2], s[na][3],
                         ah0, ah1, ah2, ah3, bh0, bh1);
                mma_bf16(s[na][0], s[na][1], s[na][2], s[na][3],
                         ah0, ah1, ah2, ah3, bl0, bl1);
                mma_bf16(s[na][0], s[na][1], s[na][2], s[na][3],
                         al0, al1, al2, al3, bh0, bh1);
            }
        }

        // ---- exp (no max-sub), row-sum, tf32 round ----
        float p[4][4];
#pragma unroll
        for (int na = 0; na < 4; na++) {
            float e0 = __expf(s[na][0] * scale);
            float e1 = __expf(s[na][1] * scale);
            float e2 = __expf(s[na][2] * scale);
            float e3 = __expf(s[na][3] * scale);
            l0 += e0 + e1;
            l1 += e2 + e3;
            p[na][0] = to_tf32(e0); p[na][1] = to_tf32(e1);
            p[na][2] = to_tf32(e2); p[na][3] = to_tf32(e3);
        }

        // ---- remap exp(S) D-frags -> A-frags; accumulate O_c, O_p (tf32) ----
        const int srcA = gp * 4 + (tg >> 1);
        const int srcB = srcA + 2;
        const bool odd = tg & 1;
#pragma unroll
        for (int ka = 0; ka < 4; ka++) {
            float t0, t1;
            t0 = __shfl_sync(~0u, p[ka][0], srcA);
            t1 = __shfl_sync(~0u, p[ka][1], srcA);
            float a0 = odd ? t1 : t0;
            t0 = __shfl_sync(~0u, p[ka][2], srcA);
            t1 = __shfl_sync(~0u, p[ka][3], srcA);
            float a1 = odd ? t1 : t0;
            t0 = __shfl_sync(~0u, p[ka][0], srcB);
            t1 = __shfl_sync(~0u, p[ka][1], srcB);
            float a2 = odd ? t1 : t0;
            t0 = __shfl_sync(~0u, p[ka][2], srcB);
            t1 = __shfl_sync(~0u, p[ka][3], srcB);
            float a3 = odd ? t1 : t0;

            const int pr = (wm + gp) * QS + wh * 32 + ka * 8 + tg;
            float pa0 = ps[pr];
            float pa1 = ps[pr + 8 * QS];
            float pa2 = ps[pr + 4];
            float pa3 = ps[pr + 8 * QS + 4];

            const int kr = (wh * 32 + ka * 8 + tg) * KS;
#pragma unroll
            for (int nv = 0; nv < 8; nv++) {
                float b0 = vs[kr + nv * 8 + gp];
                float b1 = vs[kr + 4 * KS + nv * 8 + gp];
                mma_tf32(Oc[nv][0], Oc[nv][1], Oc[nv][2], Oc[nv][3],
                         a0, a1, a2, a3, b0, b1);
                mma_tf32(Op[nv][0], Op[nv][1], Op[nv][2], Op[nv][3],
                         pa0, pa1, pa2, pa3, b0, b1);
            }
        }
    }

    // ---- reduce row-sums within tg group ----
    l0 += __shfl_xor_sync(~0u, l0, 1); l0 += __shfl_xor_sync(~0u, l0, 2);
    l1 += __shfl_xor_sync(~0u, l1, 1); l1 += __shfl_xor_sync(~0u, l1, 2);

    // ---- combine warp-half partials (reuse vs, ps, qsb_h as scratch) ----
    float* lbuf = (float*)qsb_h;
    __syncthreads();
    if (wh == 1) {
#pragma unroll
        for (int nv = 0; nv < 8; nv++) {
            const int bc = (wm + gp) * KS + nv * 8 + 2 * tg;
            vs[bc]              = Oc[nv][0];
            vs[bc + 1]          = Oc[nv][1];
            vs[bc + 8 * KS]     = Oc[nv][2];
            vs[bc + 8 * KS + 1] = Oc[nv][3];
            const int bp = (wm + gp) * QS + nv * 8 + 2 * tg;
            ps[bp]              = Op[nv][0];
            ps[bp + 1]          = Op[nv][1];
            ps[bp + 8 * QS]     = Op[nv][2];
            ps[bp + 8 * QS + 1] = Op[nv][3];
        }
        lbuf[wm + gp] = l0;
        lbuf[wm + gp + 8] = l1;
    }
    __syncthreads();
    if (wh == 0) {
        const float g = 1.0f / (1.0f + __expf(-gating[h]));
        const float og = 1.0f - g;
        const float lt0 = l0 + lbuf[wm + gp];
        const float lt1 = l1 + lbuf[wm + gp + 8];
        const float c0 = og / lt0, c1 = og / lt1;
        const long row = n0 + wm + gp;
        float* dst0 = o + ((long)b * NN + row) * DD + h * 64;
#pragma unroll
        for (int nv = 0; nv < 8; nv++) {
            const int bc = (wm + gp) * KS + nv * 8 + 2 * tg;
            const int bp = (wm + gp) * QS + nv * 8 + 2 * tg;
            float oc0 = Oc[nv][0] + vs[bc];
            float oc1 = Oc[nv][1] + vs[bc + 1];
            float oc2 = Oc[nv][2] + vs[bc + 8 * KS];
            float oc3 = Oc[nv][3] + vs[bc + 8 * KS + 1];
            float op0 = Op[nv][0] + ps[bp];
            float op1 = Op[nv][1] + ps[bp + 1];
            float op2 = Op[nv][2] + ps[bp + 8 * QS];
            float op3 = Op[nv][3] + ps[bp + 8 * QS + 1];
            float* dst = dst0 + nv * 8 + 2 * tg;
            *(float2*)dst = make_float2(c0 * oc0 + g * op0, c0 * oc1 + g * op1);
            *(float2*)(dst + 8L * DD) = make_float2(c1 * oc2 + g * op2, c1 * oc3 + g * op3);
        }
    }
}

// ---------------- launch ----------------
extern "C" void kernel_launch(void* const* d_in, const int* in_sizes, int n_in,
                              void* d_out, int out_size) {
    const float* x      = (const float*)d_in[0];
    const float* W_qk   = (const float*)d_in[1];
    const float* W_v    = (const float*)d_in[2];
    const float* W_proj = (const float*)d_in[3];
    const float* b_proj = (const float*)d_in[4];
    const float* W_pos  = (const float*)d_in[5];
    const float* b_pos  = (const float*)d_in[6];
    const float* gating = (const float*)d_in[7];
    const float* rel    = (const float*)d_in[8];
    float* out = (float*)d_out;

    float* qk;   cudaGetSymbolAddress((void**)&qk,   g_qk);
    float* vbuf; cudaGetSymbolAddress((void**)&vbuf, g_v);
    float* pos;  cudaGetSymbolAddress((void**)&pos,  g_pos);
    float* obuf; cudaGetSymbolAddress((void**)&obuf, g_o);

    cudaFuncSetAttribute(gemm_tf32<false>, cudaFuncAttributeMaxDynamicSharedMemorySize, GS_SMEM);
    cudaFuncSetAttribute(gemm_tf32<true>,  cudaFuncAttributeMaxDynamicSharedMemorySize, GS_SMEM);
    cudaFuncSetAttribute(fused_attn, cudaFuncAttributeMaxDynamicSharedMemorySize, FA_SMEM);

    const int M = BB * NN;  // 9216

    // 1) qk = x @ W_qk
    gemm_tf32<false><<<dim3(2 * DD / 128, M / 128), 256, GS_SMEM>>>(x, W_qk, nullptr, qk, M, DD, 2 * DD);
    // 2) v = x @ W_v
    gemm_tf32<false><<<dim3(DD / 128, M / 128), 256, GS_SMEM>>>(x, W_v, nullptr, vbuf, M, DD, DD);
    // 3) positional softmax
    pos_kernel<<<dim3(NN, HH), 256>>>(rel, W_pos, b_pos, pos);
    // 4) fused one-pass attention
    fused_attn<<<dim3(NN / 64, BB * HH), 256, FA_SMEM>>>(qk, vbuf, pos, gating, obuf);
    // 5) out = o @ W_proj + b_proj
    gemm_tf32<true><<<dim3(DD / 128, M / 128), 256, GS_SMEM>>>(obuf, W_proj, b_proj, out, M, DD, DD);
}